// round 6
// baseline (speedup 1.0000x reference)
#include <cuda_runtime.h>
#include <cuda_bf16.h>
#include <cstdint>

#define DIN 1024
#define HD  128
#define BM  128
#define KC  64
#define NCHUNK (DIN/KC)   // 16

// ---------------- preconverted weights (transposed + bf16 hi/lo split) -----
__device__ __nv_bfloat16 g_W0T_hi[HD*DIN];
__device__ __nv_bfloat16 g_W0T_lo[HD*DIN];
__device__ __nv_bfloat16 g_W1T_hi[HD*HD];
__device__ __nv_bfloat16 g_W1T_lo[HD*HD];
__device__ __nv_bfloat16 g_W2T_hi[HD*HD];
__device__ __nv_bfloat16 g_W2T_lo[HD*HD];

__global__ void prep_w(const float* __restrict__ W, int K, int which)
{
    __shared__ float t[32][33];
    __nv_bfloat16* hi = which==0 ? g_W0T_hi : (which==1 ? g_W1T_hi : g_W2T_hi);
    __nv_bfloat16* lo = which==0 ? g_W0T_lo : (which==1 ? g_W1T_lo : g_W2T_lo);
    int bx = blockIdx.x, by = blockIdx.y;
    int tx = threadIdx.x, ty = threadIdx.y;   // (32,8)
    #pragma unroll
    for (int r = 0; r < 32; r += 8)
        t[ty+r][tx] = W[(size_t)(bx*32 + ty + r)*HD + by*32 + tx];
    __syncthreads();
    #pragma unroll
    for (int r = 0; r < 32; r += 8) {
        int n = by*32 + ty + r;
        int k = bx*32 + tx;
        float w = t[tx][ty+r];
        __nv_bfloat16 h = __float2bfloat16(w);
        hi[(size_t)n*K + k] = h;
        lo[(size_t)n*K + k] = __float2bfloat16(w - __bfloat162float(h));
    }
}

// ---------------- helpers ---------------------------------------------------
__device__ __forceinline__ uint32_t smem_u32(const void* p) {
    uint32_t a;
    asm("{ .reg .u64 t; cvta.to.shared.u64 t, %1; cvt.u32.u64 %0, t; }" : "=r"(a) : "l"(p));
    return a;
}
__device__ __forceinline__ uint32_t sw128(uint32_t o) { return o ^ ((o >> 3) & 0x70); }
__device__ __forceinline__ uint32_t sw256(uint32_t o) { return o ^ ((o >> 4) & 0x70); }

__device__ __forceinline__ void cpasync16(uint32_t dst, const void* src) {
    asm volatile("cp.async.cg.shared.global [%0], [%1], 16;" :: "r"(dst), "l"(src));
}
#define CP_COMMIT()  asm volatile("cp.async.commit_group;" ::: "memory")
#define CP_WAIT0()   asm volatile("cp.async.wait_group 0;"  ::: "memory")

__device__ __forceinline__ void ldsm4(uint32_t addr, uint32_t* r) {
    asm volatile("ldmatrix.sync.aligned.m8n8.x4.shared.b16 {%0,%1,%2,%3}, [%4];"
        : "=r"(r[0]), "=r"(r[1]), "=r"(r[2]), "=r"(r[3]) : "r"(addr));
}
__device__ __forceinline__ void mma16816(float* c, const uint32_t* a, uint32_t b0, uint32_t b1) {
    asm volatile("mma.sync.aligned.m16n8k16.row.col.f32.bf16.bf16.f32 "
        "{%0,%1,%2,%3}, {%4,%5,%6,%7}, {%8,%9}, {%0,%1,%2,%3};"
        : "+f"(c[0]), "+f"(c[1]), "+f"(c[2]), "+f"(c[3])
        : "r"(a[0]), "r"(a[1]), "r"(a[2]), "r"(a[3]), "r"(b0), "r"(b1));
}

// ---------------- smem layout ----------------------------------------------
#define A_HI   0
#define A_LO   16384
#define B_HI   32768
#define B_LO   49152
#define RG0    0           // GEMM0 stage0; later h_hi|h_lo (rows 256B)
#define RG1    65536       // GEMM0 stage1; later W1 hi|lo
#define RG2    131072      // W2 hi|lo
#define H_HI   0
#define H_LO   32768
#define S_BIAS 196608
#define S_PART (S_BIAS + 1536)           // 2*128 floats partial sums
#define SMEM_TOTAL (S_PART + 1024)

__global__ __launch_bounds__(256)
void fused_mlp_mma(const float* __restrict__ x,
                   const float* __restrict__ b0,
                   const float* __restrict__ b1,
                   const float* __restrict__ b2,
                   float* __restrict__ out)
{
    extern __shared__ char smem[];
    const uint32_t su = smem_u32(smem);
    const int tid  = threadIdx.x;
    const int lane = tid & 31;
    const int wid  = tid >> 5;           // 8 warps: 4 in M x 2 in N
    const int wm   = wid & 3;            // M group: rows wm*32..+32
    const int wn   = wid >> 2;           // N group: cols wn*64..+64
    const int m0   = blockIdx.x * BM;

    float* b0s = (float*)(smem + S_BIAS);
    float* b1s = (float*)(smem + S_BIAS + 512);
    float* b2s = (float*)(smem + S_BIAS + 1024);
    float* part = (float*)(smem + S_PART);      // [2][128]
    if (tid < HD) { b0s[tid] = b0[tid]; b1s[tid] = b1[tid]; b2s[tid] = b2[tid]; }

    // ldmatrix lane addressing
    const uint32_t aLane   = (uint32_t)(lane & 15);
    const uint32_t aColSel = (uint32_t)((lane >> 4) * 16);
    const uint32_t bRow    = (uint32_t)((lane & 7) + ((lane >> 4) & 1) * 8);
    const uint32_t bColSel = (uint32_t)(((lane >> 3) & 1) * 16);
    const int colbase = (lane & 3) * 2;
    const int qr = lane >> 2;            // 0..7

    // ---- loaders ----
    float4 xr[8];
    auto load_x = [&](int chunk) {
        const float* xb = x + (size_t)m0 * DIN + chunk * KC;
        #pragma unroll
        for (int j = 0; j < 8; j++) {
            int flat = j * 256 + tid;
            int row = flat >> 4, c4 = flat & 15;
            xr[j] = *(const float4*)(xb + (size_t)row * DIN + c4 * 4);
        }
    };
    auto sts_A = [&](uint32_t stage_base) {
        #pragma unroll
        for (int j = 0; j < 8; j++) {
            int flat = j * 256 + tid;
            int row = flat >> 4, c4 = flat & 15;
            float4 f = xr[j];
            __nv_bfloat162 h01 = __floats2bfloat162_rn(f.x, f.y);
            __nv_bfloat162 h23 = __floats2bfloat162_rn(f.z, f.w);
            __nv_bfloat162 l01 = __floats2bfloat162_rn(f.x - __low2float(h01), f.y - __high2float(h01));
            __nv_bfloat162 l23 = __floats2bfloat162_rn(f.z - __low2float(h23), f.w - __high2float(h23));
            uint32_t off = sw128((uint32_t)(row * 128 + c4 * 8));
            uint2 hv = { *(uint32_t*)&h01, *(uint32_t*)&h23 };
            uint2 lv = { *(uint32_t*)&l01, *(uint32_t*)&l23 };
            *(uint2*)(smem + stage_base + A_HI + off) = hv;
            *(uint2*)(smem + stage_base + A_LO + off) = lv;
        }
    };
    auto cp_B = [&](int chunk, uint32_t stage_base) {
        const int k0 = chunk * KC;
        #pragma unroll
        for (int j = 0; j < 4; j++) {
            int flat = j * 256 + tid;
            int row = flat >> 3, c8 = flat & 7;
            uint32_t off = sw128((uint32_t)(row * 128 + c8 * 16));
            cpasync16(su + stage_base + B_HI + off, g_W0T_hi + (size_t)row * DIN + k0 + c8 * 8);
            cpasync16(su + stage_base + B_LO + off, g_W0T_lo + (size_t)row * DIN + k0 + c8 * 8);
        }
    };

    float acc[2][8][4];
    #pragma unroll
    for (int a = 0; a < 2; a++)
        #pragma unroll
        for (int n = 0; n < 8; n++)
            #pragma unroll
            for (int q = 0; q < 4; q++) acc[a][n][q] = 0.f;

    // ---- GEMM0 mainloop: 2-stage ring --------------------------------------
    load_x(0);
    cp_B(0, RG0); CP_COMMIT();
    sts_A(RG0);
    load_x(1);
    CP_WAIT0();
    __syncthreads();

    for (int i = 0; i < NCHUNK; i++) {
        const uint32_t sb  = (i & 1) ? RG1 : RG0;
        const uint32_t sbn = (i & 1) ? RG0 : RG1;
        if (i < NCHUNK - 1) {
            cp_B(i + 1, sbn); CP_COMMIT();
            sts_A(sbn);
            if (i < NCHUNK - 2) load_x(i + 2);
        }
        #pragma unroll
        for (int ks = 0; ks < 4; ks++) {
            uint32_t ah[2][4], al[2][4], bh[4][4], bl[4][4];
            #pragma unroll
            for (int mi = 0; mi < 2; mi++) {
                uint32_t aoff = sw128((uint32_t)(wm*32 + mi*16 + aLane) * 128 + (uint32_t)ks * 32 + aColSel);
                ldsm4(su + sb + A_HI + aoff, ah[mi]);
                ldsm4(su + sb + A_LO + aoff, al[mi]);
            }
            #pragma unroll
            for (int nn = 0; nn < 4; nn++) {
                uint32_t boff = sw128(((uint32_t)(wn*64 + nn*16) + bRow) * 128 + (uint32_t)ks * 32 + bColSel);
                ldsm4(su + sb + B_HI + boff, bh[nn]);
                ldsm4(su + sb + B_LO + boff, bl[nn]);
            }
            #pragma unroll
            for (int mi = 0; mi < 2; mi++)
                #pragma unroll
                for (int nn = 0; nn < 4; nn++) {
                    mma16816(acc[mi][nn*2],   ah[mi], bh[nn][0], bh[nn][1]);
                    mma16816(acc[mi][nn*2],   ah[mi], bl[nn][0], bl[nn][1]);
                    mma16816(acc[mi][nn*2],   al[mi], bh[nn][0], bh[nn][1]);
                    mma16816(acc[mi][nn*2+1], ah[mi], bh[nn][2], bh[nn][3]);
                    mma16816(acc[mi][nn*2+1], ah[mi], bl[nn][2], bl[nn][3]);
                    mma16816(acc[mi][nn*2+1], al[mi], bh[nn][2], bh[nn][3]);
                }
        }
        if (i < NCHUNK - 1) {
            CP_WAIT0();
            __syncthreads();
        }
    }
    __syncthreads();

    // ---- prefetch W1/W2 into RG1/RG2 ---------------------------------------
    {
        auto cp_W = [&](const __nv_bfloat16* src, uint32_t base) {
            #pragma unroll
            for (int j = 0; j < 8; j++) {
                int flat = j * 256 + tid;
                int row = flat >> 4, c16 = flat & 15;
                uint32_t off = sw256((uint32_t)(row * 256 + c16 * 16));
                cpasync16(su + base + off, src + (size_t)row * HD + c16 * 8);
            }
        };
        cp_W(g_W1T_hi, RG1 + H_HI);
        cp_W(g_W1T_lo, RG1 + H_LO);
        cp_W(g_W2T_hi, RG2 + H_HI);
        cp_W(g_W2T_lo, RG2 + H_LO);
        CP_COMMIT();
    }

    // ---- epilogue 0: bias + rmsnorm (cross-warp), h -> smem bf16 hi/lo ----
    // thread owns rows R[i] = wm*32 + i8*8 + mi*16 + qr, cols wn*64 + nn*16 + p*8 + colbase + {0,1}
    {
        float ssp[4] = {0.f, 0.f, 0.f, 0.f};
        #pragma unroll
        for (int mi = 0; mi < 2; mi++)
            #pragma unroll
            for (int nn = 0; nn < 4; nn++)
                #pragma unroll
                for (int p = 0; p < 2; p++) {
                    float2 bv = *(float2*)&b0s[wn*64 + nn*16 + p*8 + colbase];
                    float* c = acc[mi][nn*2 + p];
                    c[0] += bv.x; c[1] += bv.y; c[2] += bv.x; c[3] += bv.y;
                    ssp[mi*2]     = fmaf(c[0], c[0], fmaf(c[1], c[1], ssp[mi*2]));
                    ssp[mi*2 + 1] = fmaf(c[2], c[2], fmaf(c[3], c[3], ssp[mi*2 + 1]));
                }
        #pragma unroll
        for (int i = 0; i < 4; i++) {
            ssp[i] += __shfl_xor_sync(0xffffffffu, ssp[i], 1);
            ssp[i] += __shfl_xor_sync(0xffffffffu, ssp[i], 2);
        }
        if ((lane & 3) == 0) {
            #pragma unroll
            for (int i = 0; i < 4; i++) {
                int r = wm*32 + (i >> 1)*16 + (i & 1)*8 + qr;
                part[wn*128 + r] = ssp[i];
            }
        }
        __syncthreads();
        #pragma unroll
        for (int i = 0; i < 4; i++) {
            int r = wm*32 + (i >> 1)*16 + (i & 1)*8 + qr;
            float ss = part[r] + part[128 + r];
            float sc = rsqrtf(ss * (1.f/128.f) + 1e-6f);
            int mi = i >> 1, half = i & 1;
            #pragma unroll
            for (int nn = 0; nn < 4; nn++)
                #pragma unroll
                for (int p = 0; p < 2; p++) {
                    float v0 = acc[mi][nn*2 + p][half*2]     * sc;
                    float v1 = acc[mi][nn*2 + p][half*2 + 1] * sc;
                    __nv_bfloat162 h2 = __floats2bfloat162_rn(v0, v1);
                    __nv_bfloat162 l2 = __floats2bfloat162_rn(v0 - __low2float(h2), v1 - __high2float(h2));
                    int col = wn*64 + nn*16 + p*8 + colbase;
                    uint32_t off = sw256((uint32_t)(r * 256 + col * 2));
                    *(uint32_t*)(smem + RG0 + H_HI + off) = *(uint32_t*)&h2;
                    *(uint32_t*)(smem + RG0 + H_LO + off) = *(uint32_t*)&l2;
                }
        }
    }
    CP_WAIT0();
    __syncthreads();

    // ---- GEMM1: acc = h @ W1 (3-pass, K=128) ------------------------------
    #pragma unroll
    for (int a = 0; a < 2; a++)
        #pragma unroll
        for (int n = 0; n < 8; n++)
            #pragma unroll
            for (int q = 0; q < 4; q++) acc[a][n][q] = 0.f;

    #pragma unroll
    for (int ks = 0; ks < 8; ks++) {
        uint32_t ah[2][4], al[2][4], bh[4][4], bl[4][4];
        #pragma unroll
        for (int mi = 0; mi < 2; mi++) {
            uint32_t aoff = sw256((uint32_t)(wm*32 + mi*16 + aLane) * 256 + (uint32_t)ks * 32 + aColSel);
            ldsm4(su + RG0 + H_HI + aoff, ah[mi]);
            ldsm4(su + RG0 + H_LO + aoff, al[mi]);
        }
        #pragma unroll
        for (int nn = 0; nn < 4; nn++) {
            uint32_t boff = sw256(((uint32_t)(wn*64 + nn*16) + bRow) * 256 + (uint32_t)ks * 32 + bColSel);
            ldsm4(su + RG1 + H_HI + boff, bh[nn]);
            ldsm4(su + RG1 + H_LO + boff, bl[nn]);
        }
        #pragma unroll
        for (int mi = 0; mi < 2; mi++)
            #pragma unroll
            for (int nn = 0; nn < 4; nn++) {
                mma16816(acc[mi][nn*2],   ah[mi], bh[nn][0], bh[nn][1]);
                mma16816(acc[mi][nn*2],   ah[mi], bl[nn][0], bl[nn][1]);
                mma16816(acc[mi][nn*2],   al[mi], bh[nn][0], bh[nn][1]);
                mma16816(acc[mi][nn*2+1], ah[mi], bh[nn][2], bh[nn][3]);
                mma16816(acc[mi][nn*2+1], ah[mi], bl[nn][2], bl[nn][3]);
                mma16816(acc[mi][nn*2+1], al[mi], bh[nn][2], bh[nn][3]);
            }
    }
    __syncthreads();   // all warps done reading h before overwrite

    // ---- epilogue 1: sigmoid + residual(from smem); h1 -> smem ------------
    #pragma unroll
    for (int mi = 0; mi < 2; mi++)
        #pragma unroll
        for (int half = 0; half < 2; half++) {
            int r = wm*32 + mi*16 + half*8 + qr;
            #pragma unroll
            for (int nn = 0; nn < 4; nn++)
                #pragma unroll
                for (int p = 0; p < 2; p++) {
                    int col = wn*64 + nn*16 + p*8 + colbase;
                    float2 bv = *(float2*)&b1s[col];
                    uint32_t off = sw256((uint32_t)(r * 256 + col * 2));
                    uint32_t hu = *(uint32_t*)(smem + RG0 + H_HI + off);
                    uint32_t lu = *(uint32_t*)(smem + RG0 + H_LO + off);
                    __nv_bfloat162 hb = *(__nv_bfloat162*)&hu;
                    __nv_bfloat162 lb = *(__nv_bfloat162*)&lu;
                    float r0 = __low2float(hb)  + __low2float(lb);
                    float r1 = __high2float(hb) + __high2float(lb);
                    float z0 = acc[mi][nn*2 + p][half*2]     + bv.x;
                    float z1 = acc[mi][nn*2 + p][half*2 + 1] + bv.y;
                    float v0 = 1.f / (1.f + __expf(-z0)) + r0;
                    float v1 = 1.f / (1.f + __expf(-z1)) + r1;
                    __nv_bfloat162 h2 = __floats2bfloat162_rn(v0, v1);
                    __nv_bfloat162 l2 = __floats2bfloat162_rn(v0 - __low2float(h2), v1 - __high2float(h2));
                    *(uint32_t*)(smem + RG0 + H_HI + off) = *(uint32_t*)&h2;
                    *(uint32_t*)(smem + RG0 + H_LO + off) = *(uint32_t*)&l2;
                }
        }
    __syncthreads();

    // ---- GEMM2: acc = h1 @ W2 (3-pass, K=128) -----------------------------
    #pragma unroll
    for (int a = 0; a < 2; a++)
        #pragma unroll
        for (int n = 0; n < 8; n++)
            #pragma unroll
            for (int q = 0; q < 4; q++) acc[a][n][q] = 0.f;

    #pragma unroll
    for (int ks = 0; ks < 8; ks++) {
        uint32_t ah[2][4], al[2][4], bh[4][4], bl[4][4];
        #pragma unroll
        for (int mi = 0; mi < 2; mi++) {
            uint32_t aoff = sw256((uint32_t)(wm*32 + mi*16 + aLane) * 256 + (uint32_t)ks * 32 + aColSel);
            ldsm4(su + RG0 + H_HI + aoff, ah[mi]);
            ldsm4(su + RG0 + H_LO + aoff, al[mi]);
        }
        #pragma unroll
        for (int nn = 0; nn < 4; nn++) {
            uint32_t boff = sw256(((uint32_t)(wn*64 + nn*16) + bRow) * 256 + (uint32_t)ks * 32 + bColSel);
            ldsm4(su + RG2 + H_HI + boff, bh[nn]);
            ldsm4(su + RG2 + H_LO + boff, bl[nn]);
        }
        #pragma unroll
        for (int mi = 0; mi < 2; mi++)
            #pragma unroll
            for (int nn = 0; nn < 4; nn++) {
                mma16816(acc[mi][nn*2],   ah[mi], bh[nn][0], bh[nn][1]);
                mma16816(acc[mi][nn*2],   ah[mi], bl[nn][0], bl[nn][1]);
                mma16816(acc[mi][nn*2],   al[mi], bh[nn][0], bh[nn][1]);
                mma16816(acc[mi][nn*2+1], ah[mi], bh[nn][2], bh[nn][3]);
                mma16816(acc[mi][nn*2+1], ah[mi], bl[nn][2], bl[nn][3]);
                mma16816(acc[mi][nn*2+1], al[mi], bh[nn][2], bh[nn][3]);
            }
    }

    // ---- epilogue 2: relu + residual(from smem); store --------------------
    #pragma unroll
    for (int mi = 0; mi < 2; mi++)
        #pragma unroll
        for (int half = 0; half < 2; half++) {
            int r = wm*32 + mi*16 + half*8 + qr;
            float* orow = out + (size_t)(m0 + r) * HD;
            #pragma unroll
            for (int nn = 0; nn < 4; nn++)
                #pragma unroll
                for (int p = 0; p < 2; p++) {
                    int col = wn*64 + nn*16 + p*8 + colbase;
                    float2 bv = *(float2*)&b2s[col];
                    uint32_t off = sw256((uint32_t)(r * 256 + col * 2));
                    uint32_t hu = *(uint32_t*)(smem + RG0 + H_HI + off);
                    uint32_t lu = *(uint32_t*)(smem + RG0 + H_LO + off);
                    __nv_bfloat162 hb = *(__nv_bfloat162*)&hu;
                    __nv_bfloat162 lb = *(__nv_bfloat162*)&lu;
                    float r0 = __low2float(hb)  + __low2float(lb);
                    float r1 = __high2float(hb) + __high2float(lb);
                    float2 o;
                    o.x = fmaxf(acc[mi][nn*2 + p][half*2]     + bv.x, 0.f) + r0;
                    o.y = fmaxf(acc[mi][nn*2 + p][half*2 + 1] + bv.y, 0.f) + r1;
                    *(float2*)(orow + col) = o;
                }
        }
}

// ---------------- launch ----------------------------------------------------
extern "C" void kernel_launch(void* const* d_in, const int* in_sizes, int n_in,
                              void* d_out, int out_size)
{
    const float* x  = (const float*)d_in[0];
    const float* W0 = (const float*)d_in[1];
    const float* b0 = (const float*)d_in[2];
    const float* W1 = (const float*)d_in[3];
    const float* b1 = (const float*)d_in[4];
    const float* W2 = (const float*)d_in[5];
    const float* b2 = (const float*)d_in[6];
    float* out = (float*)d_out;

    const int M = in_sizes[0] / DIN;   // 32768

    prep_w<<<dim3(DIN/32, HD/32), dim3(32, 8)>>>(W0, DIN, 0);
    prep_w<<<dim3(HD/32,  HD/32), dim3(32, 8)>>>(W1, HD, 1);
    prep_w<<<dim3(HD/32,  HD/32), dim3(32, 8)>>>(W2, HD, 2);

    cudaFuncSetAttribute(fused_mlp_mma,
                         cudaFuncAttributeMaxDynamicSharedMemorySize, SMEM_TOTAL);
    fused_mlp_mma<<<M / BM, 256, SMEM_TOTAL>>>(x, b0, b1, b2, out);
}